// round 1
// baseline (speedup 1.0000x reference)
#include <cuda_runtime.h>

#define BATCH 8
#define HH 512
#define WW 512
#define C1 32

// Scratch for intermediate h = LeakyReLU(conv1(x)) : [8,32,512,512] fp32 = 256MB
__device__ float g_h[BATCH * C1 * HH * WW];

// ---------------------------------------------------------------------------
// Kernel 1: conv 5x5 (2->32, pad 2) + bias + LeakyReLU(0.1) -> g_h
// Block: 256 threads (32x8), tile 32x32 output pixels, 4 rows per thread.
// ---------------------------------------------------------------------------
__global__ __launch_bounds__(256) void conv1_kernel(
    const float* __restrict__ img, const float* __restrict__ ref,
    const float* __restrict__ w1, const float* __restrict__ b1)
{
    __shared__ float sIn[2][36 * 36];
    __shared__ float sW[1600];   // w1: [32][2][5][5]
    __shared__ float sB[32];

    const int tid = threadIdx.x;
    const int bx = blockIdx.x, by = blockIdx.y, b = blockIdx.z;
    const int gx0 = bx * 32 - 2, gy0 = by * 32 - 2;

    const float* ib = img + b * HH * WW;
    const float* rb = ref + b * HH * WW;

    for (int i = tid; i < 36 * 36; i += 256) {
        int yy = i / 36, xx = i - yy * 36;
        int gy = gy0 + yy, gx = gx0 + xx;
        bool ok = ((unsigned)gy < HH) && ((unsigned)gx < WW);
        sIn[0][i] = ok ? ib[gy * WW + gx] : 0.f;
        sIn[1][i] = ok ? rb[gy * WW + gx] : 0.f;
    }
    for (int i = tid; i < 1600; i += 256) sW[i] = w1[i];
    if (tid < 32) sB[tid] = b1[tid];
    __syncthreads();

    const int tx = tid & 31, ty = tid >> 5;
    const int ly0 = ty * 4;
    const int gx = bx * 32 + tx;

    #pragma unroll 1
    for (int co = 0; co < 32; co += 8) {
        float acc[8][4];
        #pragma unroll
        for (int oc = 0; oc < 8; oc++) {
            float bb = sB[co + oc];
            acc[oc][0] = bb; acc[oc][1] = bb; acc[oc][2] = bb; acc[oc][3] = bb;
        }
        #pragma unroll 1
        for (int ci = 0; ci < 2; ci++) {
            #pragma unroll
            for (int dy = 0; dy < 5; dy++) {
                #pragma unroll
                for (int dx = 0; dx < 5; dx++) {
                    const float* vp = &sIn[ci][(ly0 + dy) * 36 + tx + dx];
                    float v0 = vp[0], v1 = vp[36], v2 = vp[72], v3 = vp[108];
                    int wb = ci * 25 + dy * 5 + dx;
                    #pragma unroll
                    for (int oc = 0; oc < 8; oc++) {
                        float w = sW[(co + oc) * 50 + wb];
                        acc[oc][0] += w * v0;
                        acc[oc][1] += w * v1;
                        acc[oc][2] += w * v2;
                        acc[oc][3] += w * v3;
                    }
                }
            }
        }
        #pragma unroll
        for (int oc = 0; oc < 8; oc++) {
            float* hp = g_h + ((size_t)(b * C1 + co + oc) * HH) * WW;
            #pragma unroll
            for (int r = 0; r < 4; r++) {
                float v = acc[oc][r];
                v = (v >= 0.f) ? v : 0.1f * v;
                hp[(by * 32 + ly0 + r) * WW + gx] = v;
            }
        }
    }
}

// ---------------------------------------------------------------------------
// Kernel 2: conv 5x5 (32->9, pad 2) + bias -> per-pixel 3x3 filter, then
// out = sum_j filter_j * image[y + j/3 - 1, x + j%3 - 1]   (fused)
// Channels processed in chunks of 4 through shared memory.
// ---------------------------------------------------------------------------
__global__ __launch_bounds__(256) void conv2_df_kernel(
    const float* __restrict__ w2, const float* __restrict__ b2,
    const float* __restrict__ img, float* __restrict__ out)
{
    __shared__ float sH[4 * 36 * 36];  // 4-channel tile of h
    __shared__ float sW[900];          // chunk weights, layout [(c*25+k)*9 + j]
    __shared__ float sImg[34 * 34];    // image tile for the dynamic-filter apply

    const int tid = threadIdx.x;
    const int bx = blockIdx.x, by = blockIdx.y, b = blockIdx.z;
    const int gx0 = bx * 32 - 2, gy0 = by * 32 - 2;
    const int ix0 = bx * 32 - 1, iy0 = by * 32 - 1;

    const float* ib = img + b * HH * WW;
    for (int i = tid; i < 34 * 34; i += 256) {
        int yy = i / 34, xx = i - yy * 34;
        int gy = iy0 + yy, gx = ix0 + xx;
        sImg[i] = (((unsigned)gy < HH) && ((unsigned)gx < WW)) ? ib[gy * WW + gx] : 0.f;
    }

    const int tx = tid & 31, ty = tid >> 5;
    const int ly0 = ty * 4;

    float filt[9][4];
    #pragma unroll
    for (int j = 0; j < 9; j++)
        #pragma unroll
        for (int r = 0; r < 4; r++) filt[j][r] = 0.f;

    #pragma unroll 1
    for (int cc = 0; cc < 8; cc++) {
        __syncthreads();
        // load 4 channels of h (with conv padding) into smem
        for (int i = tid; i < 4 * 1296; i += 256) {
            int c = i / 1296, rem = i - c * 1296;
            int yy = rem / 36, xx = rem - yy * 36;
            int gy = gy0 + yy, gx = gx0 + xx;
            sH[i] = (((unsigned)gy < HH) && ((unsigned)gx < WW))
                        ? g_h[((size_t)(b * C1 + cc * 4 + c) * HH + gy) * WW + gx]
                        : 0.f;
        }
        // load chunk weights, transposed so j is contiguous
        for (int i = tid; i < 900; i += 256) {
            int t = i / 9, j = i - t * 9;
            int c = t / 25, k = t - c * 25;
            sW[i] = w2[(j * C1 + cc * 4 + c) * 25 + k];
        }
        __syncthreads();

        #pragma unroll 1
        for (int c = 0; c < 4; c++) {
            #pragma unroll
            for (int dy = 0; dy < 5; dy++) {
                #pragma unroll
                for (int dx = 0; dx < 5; dx++) {
                    const float* hp = &sH[c * 1296 + (ly0 + dy) * 36 + tx + dx];
                    float v0 = hp[0], v1 = hp[36], v2 = hp[72], v3 = hp[108];
                    const float* wp = &sW[(c * 25 + dy * 5 + dx) * 9];
                    #pragma unroll
                    for (int j = 0; j < 9; j++) {
                        float w = wp[j];
                        filt[j][0] += w * v0;
                        filt[j][1] += w * v1;
                        filt[j][2] += w * v2;
                        filt[j][3] += w * v3;
                    }
                }
            }
        }
    }

    // epilogue: add bias, apply dynamic 3x3 filter against image tile
    float o[4] = {0.f, 0.f, 0.f, 0.f};
    #pragma unroll
    for (int j = 0; j < 9; j++) {
        float bj = __ldg(&b2[j]);
        int dy = j / 3, dx = j - dy * 3;
        #pragma unroll
        for (int r = 0; r < 4; r++) {
            float f = filt[j][r] + bj;
            o[r] += f * sImg[(ly0 + r + dy) * 34 + tx + dx];
        }
    }

    const int gx = bx * 32 + tx;
    #pragma unroll
    for (int r = 0; r < 4; r++)
        out[((size_t)b * HH + by * 32 + ly0 + r) * WW + gx] = o[r];
}

extern "C" void kernel_launch(void* const* d_in, const int* in_sizes, int n_in,
                              void* d_out, int out_size) {
    const float* image = (const float*)d_in[0];
    const float* refer = (const float*)d_in[1];
    const float* w1    = (const float*)d_in[2];
    const float* b1    = (const float*)d_in[3];
    const float* w2    = (const float*)d_in[4];
    const float* b2    = (const float*)d_in[5];
    float* out = (float*)d_out;

    dim3 grid(WW / 32, HH / 32, BATCH);
    dim3 block(256);
    conv1_kernel<<<grid, block>>>(image, refer, w1, b1);
    conv2_df_kernel<<<grid, block>>>(w2, b2, image, out);
}

// round 2
// speedup vs baseline: 1.4294x; 1.4294x over previous
#include <cuda_runtime.h>

#define BATCH 8
#define HH 512
#define WW 512

// Scratch: h = LeakyReLU(conv1(x)) : [8,32,512,512] fp32 = 256MB (NCHW)
__device__ float g_h[(size_t)BATCH * 32 * HH * WW];

typedef unsigned long long u64;

__device__ __forceinline__ u64 pk2(float lo, float hi) {
    u64 r; asm("mov.b64 %0, {%1, %2};" : "=l"(r) : "f"(lo), "f"(hi)); return r;
}
__device__ __forceinline__ void upk2(u64 p, float& lo, float& hi) {
    asm("mov.b64 {%0, %1}, %2;" : "=f"(lo), "=f"(hi) : "l"(p));
}
#define FMA2(acc, w, v) asm("fma.rn.f32x2 %0, %1, %2, %0;" : "+l"(acc) : "l"(w), "l"(v))
__device__ __forceinline__ u64 add2(u64 a, u64 b) {
    u64 r; asm("add.rn.f32x2 %0, %1, %2;" : "=l"(r) : "l"(a), "l"(b)); return r;
}

// ---------------------------------------------------------------------------
// Kernel 1: conv5x5 (2->32, pad2) + bias + LeakyReLU(0.1) -> g_h
// 256 threads, tile 32x32, each thread: 1 row x 4 cols (2 f32x2 pairs).
// ---------------------------------------------------------------------------
__global__ __launch_bounds__(256, 1) void conv1_kernel(
    const float* __restrict__ img, const float* __restrict__ ref,
    const float* __restrict__ w1, const float* __restrict__ b1)
{
    __shared__ __align__(16) float sIn[2][36 * 40];
    __shared__ __align__(16) u64 sW[50 * 32];   // [(ci*25+k)*32+oc] dup pairs

    const int tid = threadIdx.x;
    const int bx = blockIdx.x, by = blockIdx.y, b = blockIdx.z;
    const int gx0 = bx * 32 - 2, gy0 = by * 32 - 2;

    const float* ib = img + (size_t)b * HH * WW;
    const float* rb = ref + (size_t)b * HH * WW;

    for (int i = tid; i < 36 * 40; i += 256) {
        int yy = i / 40, xx = i - yy * 40;
        int gy = gy0 + yy, gx = gx0 + xx;
        bool ok = ((unsigned)gy < HH) && ((unsigned)gx < WW) && (xx < 36);
        sIn[0][i] = ok ? ib[gy * WW + gx] : 0.f;
        sIn[1][i] = ok ? rb[gy * WW + gx] : 0.f;
    }
    for (int i = tid; i < 1600; i += 256) {
        int t = i >> 5, oc = i & 31;
        int ci = t / 25, k = t - ci * 25;
        float w = w1[(oc * 2 + ci) * 25 + k];
        sW[i] = pk2(w, w);
    }
    __syncthreads();

    const int lx0 = (tid & 7) * 4, ly = tid >> 3;
    const int ox = bx * 32 + lx0, oy = by * 32 + ly;

    #pragma unroll 1
    for (int co = 0; co < 32; co += 8) {
        u64 acc[8][2];
        #pragma unroll
        for (int o = 0; o < 8; o++) { acc[o][0] = 0ull; acc[o][1] = 0ull; }

        #pragma unroll
        for (int ci = 0; ci < 2; ci++) {
            #pragma unroll
            for (int dy = 0; dy < 5; dy++) {
                const float* rp = &sIn[ci][(ly + dy) * 40 + lx0];
                float4 a0 = *(const float4*)rp;
                float4 a1 = *(const float4*)(rp + 4);
                u64 P[7];
                P[0] = pk2(a0.x, a0.y); P[1] = pk2(a0.y, a0.z);
                P[2] = pk2(a0.z, a0.w); P[3] = pk2(a0.w, a1.x);
                P[4] = pk2(a1.x, a1.y); P[5] = pk2(a1.y, a1.z);
                P[6] = pk2(a1.z, a1.w);
                #pragma unroll
                for (int dx = 0; dx < 5; dx++) {
                    const ulonglong2* wp =
                        (const ulonglong2*)&sW[(ci * 25 + dy * 5 + dx) * 32 + co];
                    ulonglong2 wa = wp[0], wb = wp[1], wc = wp[2], wd = wp[3];
                    u64 vlo = P[dx], vhi = P[dx + 2];
                    FMA2(acc[0][0], wa.x, vlo); FMA2(acc[0][1], wa.x, vhi);
                    FMA2(acc[1][0], wa.y, vlo); FMA2(acc[1][1], wa.y, vhi);
                    FMA2(acc[2][0], wb.x, vlo); FMA2(acc[2][1], wb.x, vhi);
                    FMA2(acc[3][0], wb.y, vlo); FMA2(acc[3][1], wb.y, vhi);
                    FMA2(acc[4][0], wc.x, vlo); FMA2(acc[4][1], wc.x, vhi);
                    FMA2(acc[5][0], wc.y, vlo); FMA2(acc[5][1], wc.y, vhi);
                    FMA2(acc[6][0], wd.x, vlo); FMA2(acc[6][1], wd.x, vhi);
                    FMA2(acc[7][0], wd.y, vlo); FMA2(acc[7][1], wd.y, vhi);
                }
            }
        }

        #pragma unroll
        for (int o = 0; o < 8; o++) {
            float v0, v1, v2, v3;
            upk2(acc[o][0], v0, v1); upk2(acc[o][1], v2, v3);
            float bb = __ldg(&b1[co + o]);
            v0 += bb; v1 += bb; v2 += bb; v3 += bb;
            v0 = v0 >= 0.f ? v0 : 0.1f * v0;
            v1 = v1 >= 0.f ? v1 : 0.1f * v1;
            v2 = v2 >= 0.f ? v2 : 0.1f * v2;
            v3 = v3 >= 0.f ? v3 : 0.1f * v3;
            *(float4*)&g_h[((size_t)(b * 32 + co + o) * HH + oy) * WW + ox] =
                make_float4(v0, v1, v2, v3);
        }
    }
}

// ---------------------------------------------------------------------------
// Kernel 2: conv5x5 (32->9, pad2) + bias -> 3x3 dynamic filter, fused apply.
// 256 threads, tile 32x32, each thread: 1 row x 4 cols. Channels 2 at a time.
// ---------------------------------------------------------------------------
__global__ __launch_bounds__(256, 1) void conv2_df_kernel(
    const float* __restrict__ w2, const float* __restrict__ b2,
    const float* __restrict__ img, float* __restrict__ out)
{
    __shared__ __align__(16) float sH[2 * 36 * 40];
    __shared__ __align__(16) u64 sW2[500];      // [(c*25+k)*10 + j] dup pairs
    __shared__ __align__(16) float sImg[34 * 36];

    const int tid = threadIdx.x;
    const int bx = blockIdx.x, by = blockIdx.y, b = blockIdx.z;
    const int gx0 = bx * 32 - 2, gy0 = by * 32 - 2;
    const int ix0 = bx * 32 - 1, iy0 = by * 32 - 1;

    const float* ib = img + (size_t)b * HH * WW;
    for (int i = tid; i < 34 * 36; i += 256) {
        int yy = i / 36, xx = i - yy * 36;
        int gy = iy0 + yy, gx = ix0 + xx;
        bool ok = ((unsigned)gy < HH) && ((unsigned)gx < WW) && (xx < 34);
        sImg[i] = ok ? ib[gy * WW + gx] : 0.f;
    }

    const int lx0 = (tid & 7) * 4, ly = tid >> 3;

    u64 f[9][2];
    #pragma unroll
    for (int j = 0; j < 9; j++) { f[j][0] = 0ull; f[j][1] = 0ull; }

    #pragma unroll 1
    for (int cc = 0; cc < 16; cc++) {
        __syncthreads();
        for (int i = tid; i < 2 * 36 * 40; i += 256) {
            int c = i / 1440, rem = i - c * 1440;
            int yy = rem / 40, xx = rem - yy * 40;
            int gy = gy0 + yy, gx = gx0 + xx;
            bool ok = ((unsigned)gy < HH) && ((unsigned)gx < WW) && (xx < 36);
            sH[i] = ok ? g_h[((size_t)(b * 32 + cc * 2 + c) * HH + gy) * WW + gx]
                       : 0.f;
        }
        for (int i = tid; i < 450; i += 256) {
            int t = i / 9, j = i - t * 9;
            int c = t / 25, k = t - c * 25;
            float w = w2[(j * 32 + cc * 2 + c) * 25 + k];
            sW2[t * 10 + j] = pk2(w, w);
        }
        __syncthreads();

        #pragma unroll
        for (int c = 0; c < 2; c++) {
            #pragma unroll
            for (int dy = 0; dy < 5; dy++) {
                const float* rp = &sH[c * 1440 + (ly + dy) * 40 + lx0];
                float4 a0 = *(const float4*)rp;
                float4 a1 = *(const float4*)(rp + 4);
                u64 P[7];
                P[0] = pk2(a0.x, a0.y); P[1] = pk2(a0.y, a0.z);
                P[2] = pk2(a0.z, a0.w); P[3] = pk2(a0.w, a1.x);
                P[4] = pk2(a1.x, a1.y); P[5] = pk2(a1.y, a1.z);
                P[6] = pk2(a1.z, a1.w);
                #pragma unroll
                for (int dx = 0; dx < 5; dx++) {
                    const int base = (c * 25 + dy * 5 + dx) * 10;
                    const ulonglong2* wp = (const ulonglong2*)&sW2[base];
                    ulonglong2 wa = wp[0], wb = wp[1], wc = wp[2], wd = wp[3];
                    u64 w8 = sW2[base + 8];
                    u64 vlo = P[dx], vhi = P[dx + 2];
                    FMA2(f[0][0], wa.x, vlo); FMA2(f[0][1], wa.x, vhi);
                    FMA2(f[1][0], wa.y, vlo); FMA2(f[1][1], wa.y, vhi);
                    FMA2(f[2][0], wb.x, vlo); FMA2(f[2][1], wb.x, vhi);
                    FMA2(f[3][0], wb.y, vlo); FMA2(f[3][1], wb.y, vhi);
                    FMA2(f[4][0], wc.x, vlo); FMA2(f[4][1], wc.x, vhi);
                    FMA2(f[5][0], wc.y, vlo); FMA2(f[5][1], wc.y, vhi);
                    FMA2(f[6][0], wd.x, vlo); FMA2(f[6][1], wd.x, vhi);
                    FMA2(f[7][0], wd.y, vlo); FMA2(f[7][1], wd.y, vhi);
                    FMA2(f[8][0], w8,   vlo); FMA2(f[8][1], w8,   vhi);
                }
            }
        }
    }

    // Epilogue: (filter + bias) applied to 3x3 image neighborhood.
    u64 o0 = 0ull, o1 = 0ull;
    #pragma unroll
    for (int jdy = 0; jdy < 3; jdy++) {
        const float* rp = &sImg[(ly + jdy) * 36 + lx0];
        float v0 = rp[0], v1 = rp[1], v2 = rp[2], v3 = rp[3], v4 = rp[4], v5 = rp[5];
        u64 Q[5];
        Q[0] = pk2(v0, v1); Q[1] = pk2(v1, v2); Q[2] = pk2(v2, v3);
        Q[3] = pk2(v3, v4); Q[4] = pk2(v4, v5);
        #pragma unroll
        for (int jdx = 0; jdx < 3; jdx++) {
            int j = jdy * 3 + jdx;
            float bj = __ldg(&b2[j]);
            u64 bp = pk2(bj, bj);
            u64 f0 = add2(f[j][0], bp);
            u64 f1 = add2(f[j][1], bp);
            FMA2(o0, f0, Q[jdx]);
            FMA2(o1, f1, Q[jdx + 2]);
        }
    }
    float r0, r1, r2, r3;
    upk2(o0, r0, r1); upk2(o1, r2, r3);
    *(float4*)&out[((size_t)b * HH + by * 32 + ly) * WW + bx * 32 + lx0] =
        make_float4(r0, r1, r2, r3);
}

extern "C" void kernel_launch(void* const* d_in, const int* in_sizes, int n_in,
                              void* d_out, int out_size) {
    const float* image = (const float*)d_in[0];
    const float* refer = (const float*)d_in[1];
    const float* w1    = (const float*)d_in[2];
    const float* b1    = (const float*)d_in[3];
    const float* w2    = (const float*)d_in[4];
    const float* b2    = (const float*)d_in[5];
    float* out = (float*)d_out;

    dim3 grid(WW / 32, HH / 32, BATCH);
    dim3 block(256);
    conv1_kernel<<<grid, block>>>(image, refer, w1, b1);
    conv2_df_kernel<<<grid, block>>>(w2, b2, image, out);
}

// round 3
// speedup vs baseline: 1.6946x; 1.1856x over previous
#include <cuda_runtime.h>

#define BATCH 8
#define HH 512
#define WW 512

// Scratch: h = LeakyReLU(conv1(x)) : [8,32,512,512] fp32 = 256MB (NCHW)
__device__ float g_h[(size_t)BATCH * 32 * HH * WW];

typedef unsigned long long u64;

__device__ __forceinline__ u64 pk2(float lo, float hi) {
    u64 r; asm("mov.b64 %0, {%1, %2};" : "=l"(r) : "f"(lo), "f"(hi)); return r;
}
__device__ __forceinline__ void upk2(u64 p, float& lo, float& hi) {
    asm("mov.b64 {%0, %1}, %2;" : "=f"(lo), "=f"(hi) : "l"(p));
}
#define FMA2(acc, w, v) asm("fma.rn.f32x2 %0, %1, %2, %0;" : "+l"(acc) : "l"(w), "l"(v))

// ---------------------------------------------------------------------------
// Kernel 1: conv5x5 (2->32, pad2) + bias + LeakyReLU(0.1) -> g_h
// 256 threads, 32x32 tile, thread = 1 row x 4 cols.
// f32x2 pairs span two OUTPUT CHANNELS; values are duplicated pairs.
// ---------------------------------------------------------------------------
__global__ __launch_bounds__(256, 2) void conv1_kernel(
    const float* __restrict__ img, const float* __restrict__ ref,
    const float* __restrict__ w1, const float* __restrict__ b1)
{
    __shared__ __align__(16) float sIn[2][36 * 40];
    __shared__ __align__(16) u64 sW[800];  // [((q*2+ci)*25+k)*4 + p] : oc-pairs

    const int tid = threadIdx.x;
    const int bx = blockIdx.x, by = blockIdx.y, b = blockIdx.z;
    const int gx0 = bx * 32 - 2, gy0 = by * 32 - 2;

    const float* ib = img + (size_t)b * HH * WW;
    const float* rb = ref + (size_t)b * HH * WW;

    for (int i = tid; i < 36 * 40; i += 256) {
        int yy = i / 40, xx = i - yy * 40;
        int gy = gy0 + yy, gx = gx0 + xx;
        bool ok = ((unsigned)gy < HH) && ((unsigned)gx < WW) && (xx < 36);
        sIn[0][i] = ok ? ib[gy * WW + gx] : 0.f;
        sIn[1][i] = ok ? rb[gy * WW + gx] : 0.f;
    }
    // pack weights: pair p of pass q covers oc = q*8+2p, q*8+2p+1
    for (int i = tid; i < 800; i += 256) {
        int p = i & 3, t = i >> 2;
        int k = t % 25, cw = t / 25;       // cw = q*2 + ci
        int q = cw >> 1, ci = cw & 1;
        int oc = q * 8 + 2 * p;
        float wlo = w1[(oc * 2 + ci) * 25 + k];
        float whi = w1[((oc + 1) * 2 + ci) * 25 + k];
        sW[i] = pk2(wlo, whi);
    }
    __syncthreads();

    const int lx0 = (tid & 7) * 4, ly = tid >> 3;
    const int ox = bx * 32 + lx0, oy = by * 32 + ly;

    #pragma unroll 1
    for (int q = 0; q < 4; q++) {
        u64 acc[4][4];
        #pragma unroll
        for (int p = 0; p < 4; p++)
            #pragma unroll
            for (int r = 0; r < 4; r++) acc[p][r] = 0ull;

        #pragma unroll 1
        for (int ci = 0; ci < 2; ci++) {
            const u64* wbase = &sW[(q * 2 + ci) * 100];
            const float* hbase = &sIn[ci][ly * 40 + lx0];
            #pragma unroll
            for (int dy = 0; dy < 5; dy++) {
                const float* rp = hbase + dy * 40;
                float4 a0 = *(const float4*)rp;
                float4 a1 = *(const float4*)(rp + 4);
                u64 D[8];
                D[0] = pk2(a0.x, a0.x); D[1] = pk2(a0.y, a0.y);
                D[2] = pk2(a0.z, a0.z); D[3] = pk2(a0.w, a0.w);
                D[4] = pk2(a1.x, a1.x); D[5] = pk2(a1.y, a1.y);
                D[6] = pk2(a1.z, a1.z); D[7] = pk2(a1.w, a1.w);
                #pragma unroll
                for (int dx = 0; dx < 5; dx++) {
                    const ulonglong2* wp =
                        (const ulonglong2*)(wbase + (dy * 5 + dx) * 4);
                    ulonglong2 wA = wp[0], wB = wp[1];
                    #pragma unroll
                    for (int r = 0; r < 4; r++) {
                        u64 v = D[dx + r];
                        FMA2(acc[0][r], wA.x, v);
                        FMA2(acc[1][r], wA.y, v);
                        FMA2(acc[2][r], wB.x, v);
                        FMA2(acc[3][r], wB.y, v);
                    }
                }
            }
        }

        #pragma unroll
        for (int p = 0; p < 4; p++) {
            float lo[4], hi[4];
            #pragma unroll
            for (int r = 0; r < 4; r++) upk2(acc[p][r], lo[r], hi[r]);
            int oc = q * 8 + 2 * p;
            float b0 = __ldg(&b1[oc]), b1v = __ldg(&b1[oc + 1]);
            float4 v0, v1;
            float* pv0 = &v0.x; float* pv1 = &v1.x;
            #pragma unroll
            for (int r = 0; r < 4; r++) {
                float a = lo[r] + b0; a = a >= 0.f ? a : 0.1f * a; pv0[r] = a;
                float c = hi[r] + b1v; c = c >= 0.f ? c : 0.1f * c; pv1[r] = c;
            }
            *(float4*)&g_h[((size_t)(b * 32 + oc) * HH + oy) * WW + ox] = v0;
            *(float4*)&g_h[((size_t)(b * 32 + oc + 1) * HH + oy) * WW + ox] = v1;
        }
    }
}

// ---------------------------------------------------------------------------
// Kernel 2: conv5x5 (32->9, pad2) + bias -> 3x3 dynamic filter, fused apply.
// f32x2 pairs span two FILTER TAPS (j, j+1); j=9 is zero-padded.
// Channels staged 4 at a time through smem.
// ---------------------------------------------------------------------------
__global__ __launch_bounds__(256, 2) void conv2_df_kernel(
    const float* __restrict__ w2, const float* __restrict__ b2,
    const float* __restrict__ img, float* __restrict__ out)
{
    __shared__ __align__(16) float sH[4 * 36 * 40];
    __shared__ __align__(16) u64 sW2[4 * 25 * 6];  // [(c*25+k)*6 + p] j-pairs
    __shared__ __align__(16) float sImg[34 * 36];

    const int tid = threadIdx.x;
    const int bx = blockIdx.x, by = blockIdx.y, b = blockIdx.z;
    const int gx0 = bx * 32 - 2, gy0 = by * 32 - 2;
    const int ix0 = bx * 32 - 1, iy0 = by * 32 - 1;

    const float* ib = img + (size_t)b * HH * WW;
    for (int i = tid; i < 34 * 36; i += 256) {
        int yy = i / 36, xx = i - yy * 36;
        int gy = iy0 + yy, gx = ix0 + xx;
        bool ok = ((unsigned)gy < HH) && ((unsigned)gx < WW) && (xx < 34);
        sImg[i] = ok ? ib[gy * WW + gx] : 0.f;
    }

    const int lx0 = (tid & 7) * 4, ly = tid >> 3;

    u64 f[5][4];   // j-pair p (j=2p,2p+1), px r
    #pragma unroll
    for (int p = 0; p < 5; p++)
        #pragma unroll
        for (int r = 0; r < 4; r++) f[p][r] = 0ull;

    #pragma unroll 1
    for (int cc = 0; cc < 8; cc++) {
        __syncthreads();
        for (int i = tid; i < 4 * 1440; i += 256) {
            int c = i / 1440, rem = i - c * 1440;
            int yy = rem / 40, xx = rem - yy * 40;
            int gy = gy0 + yy, gx = gx0 + xx;
            bool ok = ((unsigned)gy < HH) && ((unsigned)gx < WW) && (xx < 36);
            sH[i] = ok ? g_h[((size_t)(b * 32 + cc * 4 + c) * HH + gy) * WW + gx]
                       : 0.f;
        }
        for (int i = tid; i < 500; i += 256) {
            int p = i % 5, t = i / 5;
            int c = t / 25, k = t - c * 25;
            int ch = cc * 4 + c;
            int j0 = 2 * p;
            float wlo = w2[(j0 * 32 + ch) * 25 + k];
            float whi = (j0 + 1 < 9) ? w2[((j0 + 1) * 32 + ch) * 25 + k] : 0.f;
            sW2[t * 6 + p] = pk2(wlo, whi);
        }
        __syncthreads();

        #pragma unroll 1
        for (int c = 0; c < 4; c++) {
            const u64* wbase = &sW2[c * 150];
            const float* hbase = &sH[c * 1440 + ly * 40 + lx0];
            #pragma unroll
            for (int dy = 0; dy < 5; dy++) {
                const float* rp = hbase + dy * 40;
                float4 a0 = *(const float4*)rp;
                float4 a1 = *(const float4*)(rp + 4);
                u64 D[8];
                D[0] = pk2(a0.x, a0.x); D[1] = pk2(a0.y, a0.y);
                D[2] = pk2(a0.z, a0.z); D[3] = pk2(a0.w, a0.w);
                D[4] = pk2(a1.x, a1.x); D[5] = pk2(a1.y, a1.y);
                D[6] = pk2(a1.z, a1.z); D[7] = pk2(a1.w, a1.w);
                #pragma unroll
                for (int dx = 0; dx < 5; dx++) {
                    const u64* wq = wbase + (dy * 5 + dx) * 6;
                    ulonglong2 wA = *(const ulonglong2*)wq;
                    ulonglong2 wB = *(const ulonglong2*)(wq + 2);
                    u64 w4 = wq[4];
                    #pragma unroll
                    for (int r = 0; r < 4; r++) {
                        u64 v = D[dx + r];
                        FMA2(f[0][r], wA.x, v);
                        FMA2(f[1][r], wA.y, v);
                        FMA2(f[2][r], wB.x, v);
                        FMA2(f[3][r], wB.y, v);
                        FMA2(f[4][r], w4,   v);
                    }
                }
            }
        }
    }

    // Epilogue: unpack filters, add bias, apply 3x3 to image tile.
    float fj[9][4];
    #pragma unroll
    for (int p = 0; p < 4; p++)
        #pragma unroll
        for (int r = 0; r < 4; r++) upk2(f[p][r], fj[2 * p][r], fj[2 * p + 1][r]);
    {
        float dummy;
        #pragma unroll
        for (int r = 0; r < 4; r++) upk2(f[4][r], fj[8][r], dummy);
    }

    float o[4] = {0.f, 0.f, 0.f, 0.f};
    #pragma unroll
    for (int jdy = 0; jdy < 3; jdy++) {
        const float* rp = &sImg[(ly + jdy) * 36 + lx0];
        float v[6];
        #pragma unroll
        for (int i = 0; i < 6; i++) v[i] = rp[i];
        #pragma unroll
        for (int jdx = 0; jdx < 3; jdx++) {
            int j = jdy * 3 + jdx;
            float bj = __ldg(&b2[j]);
            #pragma unroll
            for (int r = 0; r < 4; r++)
                o[r] += (fj[j][r] + bj) * v[jdx + r];
        }
    }
    *(float4*)&out[((size_t)b * HH + by * 32 + ly) * WW + bx * 32 + lx0] =
        make_float4(o[0], o[1], o[2], o[3]);
}

extern "C" void kernel_launch(void* const* d_in, const int* in_sizes, int n_in,
                              void* d_out, int out_size) {
    const float* image = (const float*)d_in[0];
    const float* refer = (const float*)d_in[1];
    const float* w1    = (const float*)d_in[2];
    const float* b1    = (const float*)d_in[3];
    const float* w2    = (const float*)d_in[4];
    const float* b2    = (const float*)d_in[5];
    float* out = (float*)d_out;

    dim3 grid(WW / 32, HH / 32, BATCH);
    dim3 block(256);
    conv1_kernel<<<grid, block>>>(image, refer, w1, b1);
    conv2_df_kernel<<<grid, block>>>(w2, b2, image, out);
}

// round 4
// speedup vs baseline: 1.6982x; 1.0021x over previous
#include <cuda_runtime.h>

#define BATCH 8
#define HH 512
#define WW 512

// Scratch: h = LeakyReLU(conv1(x)) : [8,32,512,512] fp32 = 256MB (NCHW)
__device__ float g_h[(size_t)BATCH * 32 * HH * WW];

typedef unsigned long long u64;

__device__ __forceinline__ u64 pk2(float lo, float hi) {
    u64 r; asm("mov.b64 %0, {%1, %2};" : "=l"(r) : "f"(lo), "f"(hi)); return r;
}
__device__ __forceinline__ void upk2(u64 p, float& lo, float& hi) {
    asm("mov.b64 {%0, %1}, %2;" : "=f"(lo), "=f"(hi) : "l"(p));
}
#define FMA2(acc, w, v) asm("fma.rn.f32x2 %0, %1, %2, %0;" : "+l"(acc) : "l"(w), "l"(v))

// ---------------------------------------------------------------------------
// Kernel 1: conv5x5 (2->32, pad2) + bias + LeakyReLU(0.1) -> g_h
// 256 threads, 32x32 tile, thread = 1 row x 4 cols.
// f32x2 pairs span two OUTPUT CHANNELS; values are duplicated pairs.
// ---------------------------------------------------------------------------
__global__ __launch_bounds__(256, 2) void conv1_kernel(
    const float* __restrict__ img, const float* __restrict__ ref,
    const float* __restrict__ w1, const float* __restrict__ b1)
{
    __shared__ __align__(16) float sIn[2][36 * 40];
    __shared__ __align__(16) u64 sW[800];  // [((q*2+ci)*25+k)*4 + p] : oc-pairs

    const int tid = threadIdx.x;
    const int bx = blockIdx.x, by = blockIdx.y, b = blockIdx.z;
    const int gx0 = bx * 32 - 2, gy0 = by * 32 - 2;

    const float* ib = img + (size_t)b * HH * WW;
    const float* rb = ref + (size_t)b * HH * WW;

    for (int i = tid; i < 36 * 40; i += 256) {
        int yy = i / 40, xx = i - yy * 40;
        int gy = gy0 + yy, gx = gx0 + xx;
        bool ok = ((unsigned)gy < HH) && ((unsigned)gx < WW) && (xx < 36);
        sIn[0][i] = ok ? ib[gy * WW + gx] : 0.f;
        sIn[1][i] = ok ? rb[gy * WW + gx] : 0.f;
    }
    // pack weights: pair p of pass q covers oc = q*8+2p, q*8+2p+1
    for (int i = tid; i < 800; i += 256) {
        int p = i & 3, t = i >> 2;
        int k = t % 25, cw = t / 25;       // cw = q*2 + ci
        int q = cw >> 1, ci = cw & 1;
        int oc = q * 8 + 2 * p;
        float wlo = w1[(oc * 2 + ci) * 25 + k];
        float whi = w1[((oc + 1) * 2 + ci) * 25 + k];
        sW[i] = pk2(wlo, whi);
    }
    __syncthreads();

    const int lx0 = (tid & 7) * 4, ly = tid >> 3;
    const int ox = bx * 32 + lx0, oy = by * 32 + ly;

    #pragma unroll 1
    for (int q = 0; q < 4; q++) {
        u64 acc[4][4];
        #pragma unroll
        for (int p = 0; p < 4; p++)
            #pragma unroll
            for (int r = 0; r < 4; r++) acc[p][r] = 0ull;

        #pragma unroll 1
        for (int ci = 0; ci < 2; ci++) {
            const u64* wbase = &sW[(q * 2 + ci) * 100];
            const float* hbase = &sIn[ci][ly * 40 + lx0];
            #pragma unroll
            for (int dy = 0; dy < 5; dy++) {
                const float* rp = hbase + dy * 40;
                float4 a0 = *(const float4*)rp;
                float4 a1 = *(const float4*)(rp + 4);
                u64 D[8];
                D[0] = pk2(a0.x, a0.x); D[1] = pk2(a0.y, a0.y);
                D[2] = pk2(a0.z, a0.z); D[3] = pk2(a0.w, a0.w);
                D[4] = pk2(a1.x, a1.x); D[5] = pk2(a1.y, a1.y);
                D[6] = pk2(a1.z, a1.z); D[7] = pk2(a1.w, a1.w);
                #pragma unroll
                for (int dx = 0; dx < 5; dx++) {
                    const ulonglong2* wp =
                        (const ulonglong2*)(wbase + (dy * 5 + dx) * 4);
                    ulonglong2 wA = wp[0], wB = wp[1];
                    #pragma unroll
                    for (int r = 0; r < 4; r++) {
                        u64 v = D[dx + r];
                        FMA2(acc[0][r], wA.x, v);
                        FMA2(acc[1][r], wA.y, v);
                        FMA2(acc[2][r], wB.x, v);
                        FMA2(acc[3][r], wB.y, v);
                    }
                }
            }
        }

        #pragma unroll
        for (int p = 0; p < 4; p++) {
            float lo[4], hi[4];
            #pragma unroll
            for (int r = 0; r < 4; r++) upk2(acc[p][r], lo[r], hi[r]);
            int oc = q * 8 + 2 * p;
            float b0 = __ldg(&b1[oc]), b1v = __ldg(&b1[oc + 1]);
            float4 v0, v1;
            float* pv0 = &v0.x; float* pv1 = &v1.x;
            #pragma unroll
            for (int r = 0; r < 4; r++) {
                float a = lo[r] + b0; a = a >= 0.f ? a : 0.1f * a; pv0[r] = a;
                float c = hi[r] + b1v; c = c >= 0.f ? c : 0.1f * c; pv1[r] = c;
            }
            *(float4*)&g_h[((size_t)(b * 32 + oc) * HH + oy) * WW + ox] = v0;
            *(float4*)&g_h[((size_t)(b * 32 + oc + 1) * HH + oy) * WW + ox] = v1;
        }
    }
}

// ---------------------------------------------------------------------------
// Kernel 2: conv5x5 (32->9, pad2) + bias -> 3x3 dynamic filter, fused apply.
// f32x2 pairs span two FILTER TAPS (j, j+1); j=9 is zero-padded.
// Channels staged 4 at a time through smem.
// ---------------------------------------------------------------------------
__global__ __launch_bounds__(256, 2) void conv2_df_kernel(
    const float* __restrict__ w2, const float* __restrict__ b2,
    const float* __restrict__ img, float* __restrict__ out)
{
    __shared__ __align__(16) float sH[4 * 36 * 40];
    __shared__ __align__(16) u64 sW2[4 * 25 * 6];  // [(c*25+k)*6 + p] j-pairs
    __shared__ __align__(16) float sImg[34 * 36];

    const int tid = threadIdx.x;
    const int bx = blockIdx.x, by = blockIdx.y, b = blockIdx.z;
    const int gx0 = bx * 32 - 2, gy0 = by * 32 - 2;
    const int ix0 = bx * 32 - 1, iy0 = by * 32 - 1;

    const float* ib = img + (size_t)b * HH * WW;
    for (int i = tid; i < 34 * 36; i += 256) {
        int yy = i / 36, xx = i - yy * 36;
        int gy = iy0 + yy, gx = ix0 + xx;
        bool ok = ((unsigned)gy < HH) && ((unsigned)gx < WW) && (xx < 34);
        sImg[i] = ok ? ib[gy * WW + gx] : 0.f;
    }

    const int lx0 = (tid & 7) * 4, ly = tid >> 3;

    u64 f[5][4];   // j-pair p (j=2p,2p+1), px r
    #pragma unroll
    for (int p = 0; p < 5; p++)
        #pragma unroll
        for (int r = 0; r < 4; r++) f[p][r] = 0ull;

    #pragma unroll 1
    for (int cc = 0; cc < 8; cc++) {
        __syncthreads();
        for (int i = tid; i < 4 * 1440; i += 256) {
            int c = i / 1440, rem = i - c * 1440;
            int yy = rem / 40, xx = rem - yy * 40;
            int gy = gy0 + yy, gx = gx0 + xx;
            bool ok = ((unsigned)gy < HH) && ((unsigned)gx < WW) && (xx < 36);
            sH[i] = ok ? g_h[((size_t)(b * 32 + cc * 4 + c) * HH + gy) * WW + gx]
                       : 0.f;
        }
        for (int i = tid; i < 500; i += 256) {
            int p = i % 5, t = i / 5;
            int c = t / 25, k = t - c * 25;
            int ch = cc * 4 + c;
            int j0 = 2 * p;
            float wlo = w2[(j0 * 32 + ch) * 25 + k];
            float whi = (j0 + 1 < 9) ? w2[((j0 + 1) * 32 + ch) * 25 + k] : 0.f;
            sW2[t * 6 + p] = pk2(wlo, whi);
        }
        __syncthreads();

        #pragma unroll 1
        for (int c = 0; c < 4; c++) {
            const u64* wbase = &sW2[c * 150];
            const float* hbase = &sH[c * 1440 + ly * 40 + lx0];
            #pragma unroll
            for (int dy = 0; dy < 5; dy++) {
                const float* rp = hbase + dy * 40;
                float4 a0 = *(const float4*)rp;
                float4 a1 = *(const float4*)(rp + 4);
                u64 D[8];
                D[0] = pk2(a0.x, a0.x); D[1] = pk2(a0.y, a0.y);
                D[2] = pk2(a0.z, a0.z); D[3] = pk2(a0.w, a0.w);
                D[4] = pk2(a1.x, a1.x); D[5] = pk2(a1.y, a1.y);
                D[6] = pk2(a1.z, a1.z); D[7] = pk2(a1.w, a1.w);
                #pragma unroll
                for (int dx = 0; dx < 5; dx++) {
                    const u64* wq = wbase + (dy * 5 + dx) * 6;
                    ulonglong2 wA = *(const ulonglong2*)wq;
                    ulonglong2 wB = *(const ulonglong2*)(wq + 2);
                    u64 w4 = wq[4];
                    #pragma unroll
                    for (int r = 0; r < 4; r++) {
                        u64 v = D[dx + r];
                        FMA2(f[0][r], wA.x, v);
                        FMA2(f[1][r], wA.y, v);
                        FMA2(f[2][r], wB.x, v);
                        FMA2(f[3][r], wB.y, v);
                        FMA2(f[4][r], w4,   v);
                    }
                }
            }
        }
    }

    // Epilogue: unpack filters, add bias, apply 3x3 to image tile.
    float fj[9][4];
    #pragma unroll
    for (int p = 0; p < 4; p++)
        #pragma unroll
        for (int r = 0; r < 4; r++) upk2(f[p][r], fj[2 * p][r], fj[2 * p + 1][r]);
    {
        float dummy;
        #pragma unroll
        for (int r = 0; r < 4; r++) upk2(f[4][r], fj[8][r], dummy);
    }

    float o[4] = {0.f, 0.f, 0.f, 0.f};
    #pragma unroll
    for (int jdy = 0; jdy < 3; jdy++) {
        const float* rp = &sImg[(ly + jdy) * 36 + lx0];
        float v[6];
        #pragma unroll
        for (int i = 0; i < 6; i++) v[i] = rp[i];
        #pragma unroll
        for (int jdx = 0; jdx < 3; jdx++) {
            int j = jdy * 3 + jdx;
            float bj = __ldg(&b2[j]);
            #pragma unroll
            for (int r = 0; r < 4; r++)
                o[r] += (fj[j][r] + bj) * v[jdx + r];
        }
    }
    *(float4*)&out[((size_t)b * HH + by * 32 + ly) * WW + bx * 32 + lx0] =
        make_float4(o[0], o[1], o[2], o[3]);
}

extern "C" void kernel_launch(void* const* d_in, const int* in_sizes, int n_in,
                              void* d_out, int out_size) {
    const float* image = (const float*)d_in[0];
    const float* refer = (const float*)d_in[1];
    const float* w1    = (const float*)d_in[2];
    const float* b1    = (const float*)d_in[3];
    const float* w2    = (const float*)d_in[4];
    const float* b2    = (const float*)d_in[5];
    float* out = (float*)d_out;

    dim3 grid(WW / 32, HH / 32, BATCH);
    dim3 block(256);
    conv1_kernel<<<grid, block>>>(image, refer, w1, b1);
    conv2_df_kernel<<<grid, block>>>(w2, b2, image, out);
}